// round 9
// baseline (speedup 1.0000x reference)
#include <cuda_runtime.h>
#include <cuda_bf16.h>

typedef unsigned long long ull;

#define Bn   512
#define Tn   256
#define Hn   256
#define HORn 22
#define BT   4
#define NC   64           // chunks: chunk C covers k = 4C..4C+3 (2 k-pairs)
#define NTHR 512
#define NCTA (Bn/BT)      // 128

// SMEM (bytes):
//   uzr_sm : uint4[32*256] = 131072   (chunks C in [0,32))
//   uh_sm  : uint2[32*256] =  65536
//   hp     : float[4*256]  =   4096
//   rhp    : float[4*256]  =   4096
//   eps    : float[256*4]  =   4096
//   part   : float[8*256]  =   8192
#define SMEM_BYTES (131072 + 65536 + 3*4096 + 8192)   // 217088

// Packed weights (bf16x2 pairs). For chunk C, column j:
//  g_uzr4[C*256+j] = { zpair(2C,j), rpair(2C,j), zpair(2C+1,j), rpair(2C+1,j) }
//  g_uh2 [C*256+j] = { hpair(2C,j), hpair(2C+1,j) }
// where zpair(k2,j) = bf16(Uz[2k2][j]) | bf16(Uz[2k2+1][j])<<16
__device__ uint4 g_uzr4[NC * 256];
__device__ uint2 g_uh2 [NC * 256];

static __device__ __forceinline__ unsigned bfp(float a, float b) {
    unsigned lo = (unsigned)__bfloat16_as_ushort(__float2bfloat16(a));
    unsigned hi = (unsigned)__bfloat16_as_ushort(__float2bfloat16(b));
    return lo | (hi << 16);
}

__global__ void ggru_pack_kernel(const float* __restrict__ Uz,
                                 const float* __restrict__ Ur,
                                 const float* __restrict__ Uh) {
    int idx = blockIdx.x * blockDim.x + threadIdx.x;   // [0, 64*256)
    if (idx >= NC * 256) return;
    int C = idx >> 8;
    int j = idx & 255;
    int k0 = 4 * C;   // rows k0..k0+3 of U feed this chunk
    uint4 w;
    w.x = bfp(Uz[(k0    ) * Hn + j], Uz[(k0 + 1) * Hn + j]);
    w.y = bfp(Ur[(k0    ) * Hn + j], Ur[(k0 + 1) * Hn + j]);
    w.z = bfp(Uz[(k0 + 2) * Hn + j], Uz[(k0 + 3) * Hn + j]);
    w.w = bfp(Ur[(k0 + 2) * Hn + j], Ur[(k0 + 3) * Hn + j]);
    g_uzr4[idx] = w;
    uint2 h;
    h.x = bfp(Uh[(k0    ) * Hn + j], Uh[(k0 + 1) * Hn + j]);
    h.y = bfp(Uh[(k0 + 2) * Hn + j], Uh[(k0 + 3) * Hn + j]);
    g_uh2[idx] = h;
}

// ---- f32x2 helpers (Blackwell packed math; PTX-only) ----
static __device__ __forceinline__ ull bfpair(unsigned w) {
    unsigned lo = w << 16;
    unsigned hi = w & 0xFFFF0000u;
    ull p;
    asm("mov.b64 %0, {%1, %2};" : "=l"(p) : "r"(lo), "r"(hi));
    return p;
}
static __device__ __forceinline__ ull fma2(ull a, ull b, ull c) {
    ull d;
    asm("fma.rn.f32x2 %0, %1, %2, %3;" : "=l"(d) : "l"(a), "l"(b), "l"(c));
    return d;
}
static __device__ __forceinline__ float red2(ull a) {
    unsigned lo, hi;
    asm("mov.b64 {%0, %1}, %2;" : "=r"(lo), "=r"(hi) : "l"(a));
    return __uint_as_float(lo) + __uint_as_float(hi);
}

static __device__ __forceinline__ float sigf(float x) {
    return __fdividef(1.0f, 1.0f + __expf(-x));
}
static __device__ __forceinline__ float tanhf_fast(float x) {
    float e = __expf(2.0f * x);
    return 1.0f - __fdividef(2.0f, e + 1.0f);
}

__global__ void __launch_bounds__(NTHR, 1)
ggru_main_kernel(const float* __restrict__ x,
                 const float* __restrict__ Wzw, const float* __restrict__ Wzb,
                 const float* __restrict__ Uzb,
                 const float* __restrict__ Wrw, const float* __restrict__ Wrb,
                 const float* __restrict__ Urb,
                 const float* __restrict__ Whw, const float* __restrict__ Whb,
                 const float* __restrict__ Uhb,
                 const float* __restrict__ Wgw, const float* __restrict__ Wgb,
                 const float* __restrict__ p_om, const float* __restrict__ p_al,
                 const float* __restrict__ p_be, const float* __restrict__ p_ga,
                 const float* __restrict__ fc1w, const float* __restrict__ fc1b,
                 const float* __restrict__ fc2w, const float* __restrict__ fc2b,
                 float* __restrict__ out) {
    extern __shared__ unsigned char smem[];
    uint4* uzr_sm = (uint4*)smem;                       // chunks [0,32)
    uint2* uh_sm  = (uint2*)(uzr_sm + 32 * 256);
    float* hp     = (float*)(uh_sm + 32 * 256);         // [r][256]
    float* rhp    = hp + 1024;
    float* eps_sm = rhp + 1024;                         // [t*4 + r]
    float* part   = eps_sm + 1024;                      // [8][256]

    const int tid = threadIdx.x;
    const int j   = tid & 255;
    const int g   = tid >> 8;          // group 0/1
    const int r0  = blockIdx.x * BT;
    const int og  = 1 - g;
    const int orow = 2 * og;           // other group's first row
    const int myrow = 2 * g;

    // ---- prologue ----
    for (int i = tid; i < 32 * 256; i += NTHR) {
        uzr_sm[i] = g_uzr4[i];
        uh_sm[i]  = g_uh2[i];
    }
    for (int i = tid; i < Tn * BT; i += NTHR) {
        int t = i >> 2, r = i & 3;
        eps_sm[i] = x[(r0 + r) * Tn + t];
    }
    for (int i = tid; i < 1024; i += NTHR) hp[i] = 0.0f;

    const float wzw = Wzw[j], wzb = Wzb[j], uzb = Uzb[j];
    const float wrw = Wrw[j], wrb = Wrb[j], urb = Urb[j];
    const float whw = Whw[j], whb = Whb[j], uhb = Uhb[j];
    const float wgw = Wgw[j], wgb = Wgb[j];

    float om_raw = p_om[0];
    float omega  = ((om_raw > 20.0f) ? om_raw : log1pf(expf(om_raw))) + 1e-6f;
    float aP     = 1.0f / (1.0f + expf(-p_al[0]));
    float bP     = (1.0f / (1.0f + expf(-p_be[0]))) * (1.0f - aP * 0.99f);
    float gam    = p_ga[0];

    float h_reg[2] = {0.f, 0.f};                 // this group's owned rows
    float epsq[BT] = {1e-6f, 1e-6f, 1e-6f, 1e-6f};
    float sigq[BT] = {1e-6f, 1e-6f, 1e-6f, 1e-6f};

    __syncthreads();

    // Chunk assignment (balanced):
    //   g=0: smem C in [0,16),  L2 C in [32,48)
    //   g=1: smem C in [16,32), L2 C in [48,64)
    const uint4* wzr_s = uzr_sm + g * 16 * 256 + j;            // smem, local c*256
    const uint4* wzr_g = g_uzr4 + (32 + g * 16) * 256 + j;     // L2
    const uint2* wh_s  = uh_sm  + g * 16 * 256 + j;
    const uint2* wh_g  = g_uh2  + (32 + g * 16) * 256 + j;
    const int Cs = g * 16;          // global chunk base for smem part
    const int Cg = 32 + g * 16;     // global chunk base for L2 part

    for (int t = 0; t < Tn; t++) {
        const float4 e4 = *(const float4*)(eps_sm + t * 4);
        float ev[BT] = {e4.x, e4.y, e4.z, e4.w};
        float gin[BT];
#pragma unroll
        for (int r = 0; r < BT; r++) {
            gin[r]  = omega + aP * epsq[r] + bP * sigq[r];
            epsq[r] = ev[r] * ev[r];
            sigq[r] = gin[r];
        }

        // ---- phase 1: z & r partial matvecs ----
        ull az[BT] = {0, 0, 0, 0};
        ull ar[BT] = {0, 0, 0, 0};
        {
            const ulonglong2* hq = (const ulonglong2*)hp;   // [r*64 + C]
#pragma unroll 8
            for (int c = 0; c < 16; c++) {
                uint4 w = wzr_s[c * 256];
                ull za = bfpair(w.x), ra = bfpair(w.y);
                ull zb = bfpair(w.z), rb = bfpair(w.w);
                int C = Cs + c;
#pragma unroll
                for (int r = 0; r < BT; r++) {
                    ulonglong2 hv = hq[r * 64 + C];
                    az[r] = fma2(za, hv.x, az[r]);
                    az[r] = fma2(zb, hv.y, az[r]);
                    ar[r] = fma2(ra, hv.x, ar[r]);
                    ar[r] = fma2(rb, hv.y, ar[r]);
                }
            }
#pragma unroll 8
            for (int c = 0; c < 16; c++) {
                uint4 w = __ldg(wzr_g + c * 256);
                ull za = bfpair(w.x), ra = bfpair(w.y);
                ull zb = bfpair(w.z), rb = bfpair(w.w);
                int C = Cg + c;
#pragma unroll
                for (int r = 0; r < BT; r++) {
                    ulonglong2 hv = hq[r * 64 + C];
                    az[r] = fma2(za, hv.x, az[r]);
                    az[r] = fma2(zb, hv.y, az[r]);
                    ar[r] = fma2(ra, hv.x, ar[r]);
                    ar[r] = fma2(rb, hv.y, ar[r]);
                }
            }
        }
        // write partials for OTHER group's rows
        part[(g * 4 + 0) * 256 + j] = red2(az[orow]);
        part[(g * 4 + 1) * 256 + j] = red2(az[orow + 1]);
        part[(g * 4 + 2) * 256 + j] = red2(ar[orow]);
        part[(g * 4 + 3) * 256 + j] = red2(ar[orow + 1]);
        __syncthreads();

        // finalize OWN rows (both groups in parallel)
        float zz[2];
#pragma unroll
        for (int rr = 0; rr < 2; rr++) {
            int r = myrow + rr;
            float sz = red2(az[r]) + part[(og * 4 + rr) * 256 + j];
            float sr = red2(ar[r]) + part[(og * 4 + 2 + rr) * 256 + j];
            float z  = sigf(sz + fmaf(ev[r], wzw, wzb) + uzb);
            float rg = sigf(sr + fmaf(ev[r], wrw, wrb) + urb);
            zz[rr] = z;
            rhp[r * 256 + j] = rg * h_reg[rr];
        }
        __syncthreads();

        // ---- phase 2: h_tilde partial matvec ----
        ull ah[BT] = {0, 0, 0, 0};
        {
            const ulonglong2* rq = (const ulonglong2*)rhp;
#pragma unroll 8
            for (int c = 0; c < 16; c++) {
                uint2 w = wh_s[c * 256];
                ull ha = bfpair(w.x), hb = bfpair(w.y);
                int C = Cs + c;
#pragma unroll
                for (int r = 0; r < BT; r++) {
                    ulonglong2 hv = rq[r * 64 + C];
                    ah[r] = fma2(ha, hv.x, ah[r]);
                    ah[r] = fma2(hb, hv.y, ah[r]);
                }
            }
#pragma unroll 8
            for (int c = 0; c < 16; c++) {
                uint2 w = __ldg(wh_g + c * 256);
                ull ha = bfpair(w.x), hb = bfpair(w.y);
                int C = Cg + c;
#pragma unroll
                for (int r = 0; r < BT; r++) {
                    ulonglong2 hv = rq[r * 64 + C];
                    ah[r] = fma2(ha, hv.x, ah[r]);
                    ah[r] = fma2(hb, hv.y, ah[r]);
                }
            }
        }
        part[(g * 2 + 0) * 256 + j] = red2(ah[orow]);
        part[(g * 2 + 1) * 256 + j] = red2(ah[orow + 1]);
        __syncthreads();

#pragma unroll
        for (int rr = 0; rr < 2; rr++) {
            int r = myrow + rr;
            float sh = red2(ah[r]) + part[(og * 2 + rr) * 256 + j];
            float ht = tanhf_fast(sh + fmaf(ev[r], whw, whb) + uhb);
            float hh = (1.0f - zz[rr]) * ht + zz[rr] * h_reg[rr];
            float gt = fmaf(gin[r], wgw, wgb);
            float hn = tanhf_fast(fmaf(gam, gt, hh));
            h_reg[rr] = hn;
            hp[r * 256 + j] = hn;
        }
        __syncthreads();
    }

    // ---- epilogue: fc1 -> relu -> fc2 -> softplus -> vol ----
    // hp holds final h [r][256]. fc1 split-k by g; hid goes into rhp.
    {
        float acc[BT] = {0.f, 0.f, 0.f, 0.f};
        const int kb = g * 128;
        for (int k = kb; k < kb + 128; k++) {
            float f = fc1w[k * Hn + j];
#pragma unroll
            for (int r = 0; r < BT; r++) acc[r] = fmaf(hp[r * 256 + k], f, acc[r]);
        }
        if (g == 1) {
#pragma unroll
            for (int r = 0; r < BT; r++) part[r * 256 + j] = acc[r];
        }
        __syncthreads();
        if (g == 0) {
            float b1 = fc1b[j];
#pragma unroll
            for (int r = 0; r < BT; r++)
                rhp[r * 256 + j] = fmaxf(acc[r] + part[r * 256 + j] + b1, 0.0f);
        }
        __syncthreads();
    }

    if (g == 0 && j < BT * HORn) {        // 88 threads
        int r = j / HORn;
        int o = j - r * HORn;
        float s = 0.0f;
        for (int k = 0; k < Hn; k++) s = fmaf(rhp[r * 256 + k], fc2w[k * HORn + o], s);
        s += fc2b[o];
        float nn = (s > 20.0f) ? s : log1pf(expf(s));
        float vb = sqrtf(sigq[r] + 1e-8f);
        float vol = vb * (1.0f + nn);
        vol = fminf(fmaxf(vol, 0.01f), 10.0f);
        out[(r0 + r) * HORn + o] = vol;
    }
    if (g == 0 && j >= BT * HORn && j < BT * HORn + BT) {
        int r = j - BT * HORn;
        out[Bn * HORn + r0 + r] = sigq[r];
    }
}

extern "C" void kernel_launch(void* const* d_in, const int* in_sizes, int n_in,
                              void* d_out, int out_size) {
    const float* x    = (const float*)d_in[0];
    const float* Wzw  = (const float*)d_in[1];
    const float* Wzb  = (const float*)d_in[2];
    const float* Uzw  = (const float*)d_in[3];
    const float* Uzb  = (const float*)d_in[4];
    const float* Wrw  = (const float*)d_in[5];
    const float* Wrb  = (const float*)d_in[6];
    const float* Urw  = (const float*)d_in[7];
    const float* Urb  = (const float*)d_in[8];
    const float* Whw  = (const float*)d_in[9];
    const float* Whb  = (const float*)d_in[10];
    const float* Uhw  = (const float*)d_in[11];
    const float* Uhb  = (const float*)d_in[12];
    const float* Wgw  = (const float*)d_in[13];
    const float* Wgb  = (const float*)d_in[14];
    const float* om   = (const float*)d_in[15];
    const float* al   = (const float*)d_in[16];
    const float* be   = (const float*)d_in[17];
    const float* ga   = (const float*)d_in[18];
    const float* fc1w = (const float*)d_in[19];
    const float* fc1b = (const float*)d_in[20];
    const float* fc2w = (const float*)d_in[21];
    const float* fc2b = (const float*)d_in[22];
    float* out = (float*)d_out;

    ggru_pack_kernel<<<(NC * 256 + 255) / 256, 256>>>(Uzw, Urw, Uhw);

    cudaFuncSetAttribute(ggru_main_kernel,
                         cudaFuncAttributeMaxDynamicSharedMemorySize, SMEM_BYTES);
    ggru_main_kernel<<<NCTA, NTHR, SMEM_BYTES>>>(
        x, Wzw, Wzb, Uzb, Wrw, Wrb, Urb, Whw, Whb, Uhb,
        Wgw, Wgb, om, al, be, ga, fc1w, fc1b, fc2w, fc2b, out);
}

// round 10
// speedup vs baseline: 1.0658x; 1.0658x over previous
#include <cuda_runtime.h>
#include <cuda_bf16.h>

typedef unsigned long long ull;

#define Bn   512
#define Tn   256
#define Hn   256
#define HORn 22
#define BT   4
#define NC   64           // chunks: chunk C covers k = 4C..4C+3 (2 k-pairs)
#define NZS  18           // zr chunks resident in smem (9 per group)
#define NTHR 512
#define NCTA (Bn/BT)      // 128

// SMEM (bytes):
//   uzr_sm : uint4[18*256] =  73728   (zr chunks 0..17)
//   uh_sm  : uint2[64*256] = 131072   (ALL uh chunks)
//   hp     : float[4*256]  =   4096
//   rhp    : float[4*256]  =   4096
//   eps    : float[256*4]  =   4096
//   part   : float[8*256]  =   8192
#define SMEM_BYTES (73728 + 131072 + 3*4096 + 8192)   // 225280

// Packed weights (bf16x2 pairs). For chunk C, column j:
//  g_uzr4[C*256+j] = { zpair(2C,j), rpair(2C,j), zpair(2C+1,j), rpair(2C+1,j) }
//  g_uh2 [C*256+j] = { hpair(2C,j), hpair(2C+1,j) }
__device__ uint4 g_uzr4[NC * 256];
__device__ uint2 g_uh2 [NC * 256];

static __device__ __forceinline__ unsigned bfp(float a, float b) {
    unsigned lo = (unsigned)__bfloat16_as_ushort(__float2bfloat16(a));
    unsigned hi = (unsigned)__bfloat16_as_ushort(__float2bfloat16(b));
    return lo | (hi << 16);
}

__global__ void ggru_pack_kernel(const float* __restrict__ Uz,
                                 const float* __restrict__ Ur,
                                 const float* __restrict__ Uh) {
    int idx = blockIdx.x * blockDim.x + threadIdx.x;   // [0, 64*256)
    if (idx >= NC * 256) return;
    int C = idx >> 8;
    int j = idx & 255;
    int k0 = 4 * C;
    uint4 w;
    w.x = bfp(Uz[(k0    ) * Hn + j], Uz[(k0 + 1) * Hn + j]);
    w.y = bfp(Ur[(k0    ) * Hn + j], Ur[(k0 + 1) * Hn + j]);
    w.z = bfp(Uz[(k0 + 2) * Hn + j], Uz[(k0 + 3) * Hn + j]);
    w.w = bfp(Ur[(k0 + 2) * Hn + j], Ur[(k0 + 3) * Hn + j]);
    g_uzr4[idx] = w;
    uint2 h;
    h.x = bfp(Uh[(k0    ) * Hn + j], Uh[(k0 + 1) * Hn + j]);
    h.y = bfp(Uh[(k0 + 2) * Hn + j], Uh[(k0 + 3) * Hn + j]);
    g_uh2[idx] = h;
}

// ---- f32x2 helpers (Blackwell packed math; PTX-only) ----
static __device__ __forceinline__ ull bfpair(unsigned w) {
    unsigned lo = w << 16;
    unsigned hi = w & 0xFFFF0000u;
    ull p;
    asm("mov.b64 %0, {%1, %2};" : "=l"(p) : "r"(lo), "r"(hi));
    return p;
}
static __device__ __forceinline__ ull fma2(ull a, ull b, ull c) {
    ull d;
    asm("fma.rn.f32x2 %0, %1, %2, %3;" : "=l"(d) : "l"(a), "l"(b), "l"(c));
    return d;
}
static __device__ __forceinline__ float red2(ull a) {
    unsigned lo, hi;
    asm("mov.b64 {%0, %1}, %2;" : "=r"(lo), "=r"(hi) : "l"(a));
    return __uint_as_float(lo) + __uint_as_float(hi);
}

// HW tanh (sm_75+, single MUFU-class op)
static __device__ __forceinline__ float tanh_ap(float x) {
    float y;
    asm("tanh.approx.f32 %0, %1;" : "=f"(y) : "f"(x));
    return y;
}
static __device__ __forceinline__ float sig_ap(float x) {
    return fmaf(0.5f, tanh_ap(0.5f * x), 0.5f);
}

__global__ void __launch_bounds__(NTHR, 1)
ggru_main_kernel(const float* __restrict__ x,
                 const float* __restrict__ Wzw, const float* __restrict__ Wzb,
                 const float* __restrict__ Uzb,
                 const float* __restrict__ Wrw, const float* __restrict__ Wrb,
                 const float* __restrict__ Urb,
                 const float* __restrict__ Whw, const float* __restrict__ Whb,
                 const float* __restrict__ Uhb,
                 const float* __restrict__ Wgw, const float* __restrict__ Wgb,
                 const float* __restrict__ p_om, const float* __restrict__ p_al,
                 const float* __restrict__ p_be, const float* __restrict__ p_ga,
                 const float* __restrict__ fc1w, const float* __restrict__ fc1b,
                 const float* __restrict__ fc2w, const float* __restrict__ fc2b,
                 float* __restrict__ out) {
    extern __shared__ unsigned char smem[];
    uint4* uzr_sm = (uint4*)smem;                       // zr chunks [0,18)
    uint2* uh_sm  = (uint2*)(uzr_sm + NZS * 256);       // ALL uh chunks
    float* hp     = (float*)(uh_sm + NC * 256);         // [r][256]
    float* rhp    = hp + 1024;
    float* eps_sm = rhp + 1024;                         // [t*4 + r]
    float* part   = eps_sm + 1024;                      // [8][256]

    const int tid = threadIdx.x;
    const int j   = tid & 255;
    const int g   = tid >> 8;          // group 0/1 (k-split)
    const int r0  = blockIdx.x * BT;
    const int og  = 1 - g;
    const int orow  = 2 * og;
    const int myrow = 2 * g;

    // ---- prologue ----
    for (int i = tid; i < NZS * 256; i += NTHR) uzr_sm[i] = g_uzr4[i];
    for (int i = tid; i < NC * 256; i += NTHR)  uh_sm[i]  = g_uh2[i];
    for (int i = tid; i < Tn * BT; i += NTHR) {
        int t = i >> 2, r = i & 3;
        eps_sm[i] = x[(r0 + r) * Tn + t];
    }
    for (int i = tid; i < 1024; i += NTHR) hp[i] = 0.0f;

    const float wzw = Wzw[j], wzb = Wzb[j], uzb = Uzb[j];
    const float wrw = Wrw[j], wrb = Wrb[j], urb = Urb[j];
    const float whw = Whw[j], whb = Whb[j], uhb = Uhb[j];
    const float wgw = Wgw[j], wgb = Wgb[j];

    float om_raw = p_om[0];
    float omega  = ((om_raw > 20.0f) ? om_raw : log1pf(expf(om_raw))) + 1e-6f;
    float aP     = 1.0f / (1.0f + expf(-p_al[0]));
    float bP     = (1.0f / (1.0f + expf(-p_be[0]))) * (1.0f - aP * 0.99f);
    float gam    = p_ga[0];

    float h_reg[2] = {0.f, 0.f};
    float epsq[BT] = {1e-6f, 1e-6f, 1e-6f, 1e-6f};
    float sigq[BT] = {1e-6f, 1e-6f, 1e-6f, 1e-6f};

    __syncthreads();

    // zr chunk assignment:
    //   g: smem chunks [9g, 9g+9), L2 chunks [18 + 23g, 18 + 23g + 23)
    const uint4* wzr_s = uzr_sm + g * 9 * 256 + j;
    const uint4* wzr_g = g_uzr4 + (NZS + g * 23) * 256 + j;
    const int CsB = g * 9;
    const int CgB = NZS + g * 23;
    // uh: all smem; group g covers chunks [32g, 32g+32)
    const uint2* wh_s = uh_sm + g * 32 * 256 + j;
    const int ChB = g * 32;

    for (int t = 0; t < Tn; t++) {
        const float4 e4 = *(const float4*)(eps_sm + t * 4);
        float ev[BT] = {e4.x, e4.y, e4.z, e4.w};
        float gin[BT];
#pragma unroll
        for (int r = 0; r < BT; r++) {
            gin[r]  = omega + aP * epsq[r] + bP * sigq[r];
            epsq[r] = ev[r] * ev[r];
            sigq[r] = gin[r];
        }

        // ---- phase 1: z & r partial matvecs (L2 chunks first, then smem) ----
        ull az[BT] = {0, 0, 0, 0};
        ull ar[BT] = {0, 0, 0, 0};
        {
            const ulonglong2* hq = (const ulonglong2*)hp;   // [r*64 + C]
#pragma unroll 8
            for (int c = 0; c < 23; c++) {
                uint4 w = __ldg(wzr_g + c * 256);
                ull za = bfpair(w.x), ra = bfpair(w.y);
                ull zb = bfpair(w.z), rb = bfpair(w.w);
                int C = CgB + c;
#pragma unroll
                for (int r = 0; r < BT; r++) {
                    ulonglong2 hv = hq[r * 64 + C];
                    az[r] = fma2(za, hv.x, az[r]);
                    az[r] = fma2(zb, hv.y, az[r]);
                    ar[r] = fma2(ra, hv.x, ar[r]);
                    ar[r] = fma2(rb, hv.y, ar[r]);
                }
            }
#pragma unroll
            for (int c = 0; c < 9; c++) {
                uint4 w = wzr_s[c * 256];
                ull za = bfpair(w.x), ra = bfpair(w.y);
                ull zb = bfpair(w.z), rb = bfpair(w.w);
                int C = CsB + c;
#pragma unroll
                for (int r = 0; r < BT; r++) {
                    ulonglong2 hv = hq[r * 64 + C];
                    az[r] = fma2(za, hv.x, az[r]);
                    az[r] = fma2(zb, hv.y, az[r]);
                    ar[r] = fma2(ra, hv.x, ar[r]);
                    ar[r] = fma2(rb, hv.y, ar[r]);
                }
            }
        }
        // exchange partials for the OTHER group's rows
        part[(g * 4 + 0) * 256 + j] = red2(az[orow]);
        part[(g * 4 + 1) * 256 + j] = red2(az[orow + 1]);
        part[(g * 4 + 2) * 256 + j] = red2(ar[orow]);
        part[(g * 4 + 3) * 256 + j] = red2(ar[orow + 1]);
        __syncthreads();

        // finalize OWN rows' gates (both groups in parallel)
        float zz[2];
#pragma unroll
        for (int rr = 0; rr < 2; rr++) {
            int r = myrow + rr;
            float sz = red2(az[r]) + part[(og * 4 + rr) * 256 + j];
            float sr = red2(ar[r]) + part[(og * 4 + 2 + rr) * 256 + j];
            float z  = sig_ap(sz + fmaf(ev[r], wzw, wzb) + uzb);
            float rg = sig_ap(sr + fmaf(ev[r], wrw, wrb) + urb);
            zz[rr] = z;
            rhp[r * 256 + j] = rg * h_reg[rr];
        }
        __syncthreads();

        // ---- phase 2: h_tilde partial matvec (all smem) ----
        ull ah[BT] = {0, 0, 0, 0};
        {
            const ulonglong2* rq = (const ulonglong2*)rhp;
#pragma unroll 8
            for (int c = 0; c < 32; c++) {
                uint2 w = wh_s[c * 256];
                ull ha = bfpair(w.x), hb = bfpair(w.y);
                int C = ChB + c;
#pragma unroll
                for (int r = 0; r < BT; r++) {
                    ulonglong2 hv = rq[r * 64 + C];
                    ah[r] = fma2(ha, hv.x, ah[r]);
                    ah[r] = fma2(hb, hv.y, ah[r]);
                }
            }
        }
        part[(g * 2 + 0) * 256 + j] = red2(ah[orow]);
        part[(g * 2 + 1) * 256 + j] = red2(ah[orow + 1]);
        __syncthreads();

#pragma unroll
        for (int rr = 0; rr < 2; rr++) {
            int r = myrow + rr;
            float sh = red2(ah[r]) + part[(og * 2 + rr) * 256 + j];
            float ht = tanh_ap(sh + fmaf(ev[r], whw, whb) + uhb);
            float hh = (1.0f - zz[rr]) * ht + zz[rr] * h_reg[rr];
            float gt = fmaf(gin[r], wgw, wgb);
            float hn = tanh_ap(fmaf(gam, gt, hh));
            h_reg[rr] = hn;
            hp[r * 256 + j] = hn;
        }
        __syncthreads();
    }

    // ---- epilogue: fc1 -> relu -> fc2 -> softplus -> vol ----
    {
        float acc[BT] = {0.f, 0.f, 0.f, 0.f};
        const int kb = g * 128;
        for (int k = kb; k < kb + 128; k++) {
            float f = fc1w[k * Hn + j];
#pragma unroll
            for (int r = 0; r < BT; r++) acc[r] = fmaf(hp[r * 256 + k], f, acc[r]);
        }
        if (g == 1) {
#pragma unroll
            for (int r = 0; r < BT; r++) part[r * 256 + j] = acc[r];
        }
        __syncthreads();
        if (g == 0) {
            float b1 = fc1b[j];
#pragma unroll
            for (int r = 0; r < BT; r++)
                rhp[r * 256 + j] = fmaxf(acc[r] + part[r * 256 + j] + b1, 0.0f);
        }
        __syncthreads();
    }

    if (g == 0 && j < BT * HORn) {        // 88 threads
        int r = j / HORn;
        int o = j - r * HORn;
        float s = 0.0f;
        for (int k = 0; k < Hn; k++) s = fmaf(rhp[r * 256 + k], fc2w[k * HORn + o], s);
        s += fc2b[o];
        float nn = (s > 20.0f) ? s : log1pf(expf(s));
        float vb = sqrtf(sigq[r] + 1e-8f);
        float vol = vb * (1.0f + nn);
        vol = fminf(fmaxf(vol, 0.01f), 10.0f);
        out[(r0 + r) * HORn + o] = vol;
    }
    if (g == 0 && j >= BT * HORn && j < BT * HORn + BT) {
        int r = j - BT * HORn;
        out[Bn * HORn + r0 + r] = sigq[r];
    }
}

extern "C" void kernel_launch(void* const* d_in, const int* in_sizes, int n_in,
                              void* d_out, int out_size) {
    const float* x    = (const float*)d_in[0];
    const float* Wzw  = (const float*)d_in[1];
    const float* Wzb  = (const float*)d_in[2];
    const float* Uzw  = (const float*)d_in[3];
    const float* Uzb  = (const float*)d_in[4];
    const float* Wrw  = (const float*)d_in[5];
    const float* Wrb  = (const float*)d_in[6];
    const float* Urw  = (const float*)d_in[7];
    const float* Urb  = (const float*)d_in[8];
    const float* Whw  = (const float*)d_in[9];
    const float* Whb  = (const float*)d_in[10];
    const float* Uhw  = (const float*)d_in[11];
    const float* Uhb  = (const float*)d_in[12];
    const float* Wgw  = (const float*)d_in[13];
    const float* Wgb  = (const float*)d_in[14];
    const float* om   = (const float*)d_in[15];
    const float* al   = (const float*)d_in[16];
    const float* be   = (const float*)d_in[17];
    const float* ga   = (const float*)d_in[18];
    const float* fc1w = (const float*)d_in[19];
    const float* fc1b = (const float*)d_in[20];
    const float* fc2w = (const float*)d_in[21];
    const float* fc2b = (const float*)d_in[22];
    float* out = (float*)d_out;

    ggru_pack_kernel<<<(NC * 256 + 255) / 256, 256>>>(Uzw, Urw, Uhw);

    cudaFuncSetAttribute(ggru_main_kernel,
                         cudaFuncAttributeMaxDynamicSharedMemorySize, SMEM_BYTES);
    ggru_main_kernel<<<NCTA, NTHR, SMEM_BYTES>>>(
        x, Wzw, Wzb, Uzb, Wrw, Wrb, Urb, Whw, Whb, Uhb,
        Wgw, Wgb, om, al, be, ga, fc1w, fc1b, fc2w, fc2b, out);
}

// round 12
// speedup vs baseline: 1.0738x; 1.0075x over previous
#include <cuda_runtime.h>
#include <cuda_bf16.h>

typedef unsigned long long ull;

#define Bn   512
#define Tn   256
#define Hn   256
#define HORn 22
#define BT   4
#define NC   64           // chunks: chunk C covers k = 4C..4C+3 (2 k-pairs)
#define NZS  18           // zr chunks resident in smem; chunks [18,64) from L2
#define NZL  (NC - NZS)   // 46
#define PF   8            // L2 weight prefetch depth (uint4 regs)
#define NTHR 512
#define NCTA (Bn/BT)      // 128

// SMEM (bytes):
//   uzr_sm : uint4[18*256] =  73728
//   uh_sm  : uint2[64*256] = 131072
//   hp     : float[4*256]  =   4096
//   rhp    : float[4*256]  =   4096
//   eps    : float[256*4]  =   4096   (reused as partial-exchange in epilogue)
//   sigq   : float[16]     =     64
#define SMEM_BYTES (73728 + 131072 + 3*4096 + 64)   // 217152

// Packed weights (bf16x2 pairs). For chunk C, column j:
//  g_uzr4[C*256+j] = { zpair(2C,j), rpair(2C,j), zpair(2C+1,j), rpair(2C+1,j) }
//  g_uh2 [C*256+j] = { hpair(2C,j), hpair(2C+1,j) }
__device__ uint4 g_uzr4[NC * 256];
__device__ uint2 g_uh2 [NC * 256];

static __device__ __forceinline__ unsigned bfp(float a, float b) {
    unsigned lo = (unsigned)__bfloat16_as_ushort(__float2bfloat16(a));
    unsigned hi = (unsigned)__bfloat16_as_ushort(__float2bfloat16(b));
    return lo | (hi << 16);
}

__global__ void ggru_pack_kernel(const float* __restrict__ Uz,
                                 const float* __restrict__ Ur,
                                 const float* __restrict__ Uh) {
    int idx = blockIdx.x * blockDim.x + threadIdx.x;   // [0, 64*256)
    if (idx >= NC * 256) return;
    int C = idx >> 8;
    int j = idx & 255;
    int k0 = 4 * C;
    uint4 w;
    w.x = bfp(Uz[(k0    ) * Hn + j], Uz[(k0 + 1) * Hn + j]);
    w.y = bfp(Ur[(k0    ) * Hn + j], Ur[(k0 + 1) * Hn + j]);
    w.z = bfp(Uz[(k0 + 2) * Hn + j], Uz[(k0 + 3) * Hn + j]);
    w.w = bfp(Ur[(k0 + 2) * Hn + j], Ur[(k0 + 3) * Hn + j]);
    g_uzr4[idx] = w;
    uint2 h;
    h.x = bfp(Uh[(k0    ) * Hn + j], Uh[(k0 + 1) * Hn + j]);
    h.y = bfp(Uh[(k0 + 2) * Hn + j], Uh[(k0 + 3) * Hn + j]);
    g_uh2[idx] = h;
}

// ---- f32x2 helpers (Blackwell packed math; PTX-only) ----
static __device__ __forceinline__ ull bfpair(unsigned w) {
    unsigned lo = w << 16;
    unsigned hi = w & 0xFFFF0000u;
    ull p;
    asm("mov.b64 %0, {%1, %2};" : "=l"(p) : "r"(lo), "r"(hi));
    return p;
}
static __device__ __forceinline__ ull fma2(ull a, ull b, ull c) {
    ull d;
    asm("fma.rn.f32x2 %0, %1, %2, %3;" : "=l"(d) : "l"(a), "l"(b), "l"(c));
    return d;
}
static __device__ __forceinline__ float red2(ull a) {
    unsigned lo, hi;
    asm("mov.b64 {%0, %1}, %2;" : "=r"(lo), "=r"(hi) : "l"(a));
    return __uint_as_float(lo) + __uint_as_float(hi);
}
static __device__ __forceinline__ float tanh_ap(float x) {
    float y;
    asm("tanh.approx.f32 %0, %1;" : "=f"(y) : "f"(x));
    return y;
}
static __device__ __forceinline__ float sig_ap(float x) {
    return fmaf(0.5f, tanh_ap(0.5f * x), 0.5f);
}
static __device__ __forceinline__ void gbar(int id) {
    asm volatile("bar.sync %0, 256;" :: "r"(id) : "memory");
}

__global__ void __launch_bounds__(NTHR, 1)
ggru_main_kernel(const float* __restrict__ x,
                 const float* __restrict__ Wzw, const float* __restrict__ Wzb,
                 const float* __restrict__ Uzb,
                 const float* __restrict__ Wrw, const float* __restrict__ Wrb,
                 const float* __restrict__ Urb,
                 const float* __restrict__ Whw, const float* __restrict__ Whb,
                 const float* __restrict__ Uhb,
                 const float* __restrict__ Wgw, const float* __restrict__ Wgb,
                 const float* __restrict__ p_om, const float* __restrict__ p_al,
                 const float* __restrict__ p_be, const float* __restrict__ p_ga,
                 const float* __restrict__ fc1w, const float* __restrict__ fc1b,
                 const float* __restrict__ fc2w, const float* __restrict__ fc2b,
                 float* __restrict__ out) {
    extern __shared__ unsigned char smem[];
    uint4* uzr_sm = (uint4*)smem;                       // zr chunks [0,18)
    uint2* uh_sm  = (uint2*)(uzr_sm + NZS * 256);       // all uh chunks
    float* hp     = (float*)(uh_sm + NC * 256);         // [r][256]
    float* rhp    = hp + 1024;
    float* eps_sm = rhp + 1024;                         // [t*4 + r]; reused as part[]
    float* sigq_sm = eps_sm + 1024;                     // [4]

    const int tid = threadIdx.x;
    const int j   = tid & 255;
    const int g   = tid >> 8;          // group 0/1: owns rows {2g, 2g+1}
    const int r0  = blockIdx.x * BT;
    const int rA  = 2 * g;
    const int rB  = 2 * g + 1;

    // ---- prologue ----
    for (int i = tid; i < NZS * 256; i += NTHR) uzr_sm[i] = g_uzr4[i];
    for (int i = tid; i < NC * 256; i += NTHR)  uh_sm[i]  = g_uh2[i];
    for (int i = tid; i < Tn * BT; i += NTHR) {
        int t = i >> 2, r = i & 3;
        eps_sm[i] = x[(r0 + r) * Tn + t];
    }
    for (int i = tid; i < 1024; i += NTHR) hp[i] = 0.0f;

    const float wzw = Wzw[j], wzb = Wzb[j], uzb = Uzb[j];
    const float wrw = Wrw[j], wrb = Wrb[j], urb = Urb[j];
    const float whw = Whw[j], whb = Whb[j], uhb = Uhb[j];
    const float wgw = Wgw[j], wgb = Wgb[j];

    float om_raw = p_om[0];
    float omega  = ((om_raw > 20.0f) ? om_raw : log1pf(expf(om_raw))) + 1e-6f;
    float aP     = 1.0f / (1.0f + expf(-p_al[0]));
    float bP     = (1.0f / (1.0f + expf(-p_be[0]))) * (1.0f - aP * 0.99f);
    float gam    = p_ga[0];

    float h_reg[2] = {0.f, 0.f};       // own rows rA, rB
    float epsq[2]  = {1e-6f, 1e-6f};
    float sigq[2]  = {1e-6f, 1e-6f};

    __syncthreads();

    const uint4* zr_s = uzr_sm + j;              // smem chunks C in [0,18)
    const uint4* zr_g = g_uzr4 + NZS * 256 + j;  // L2 chunks C in [18,64)
    const uint2* wh_s = uh_sm + j;               // all uh chunks
    const int bid = 1 + g;                       // named barrier id for this group

    // initial prefetch of first PF L2 zr chunks
    uint4 pf[PF];
#pragma unroll
    for (int p = 0; p < PF; p++) pf[p] = __ldg(zr_g + p * 256);

    for (int t = 0; t < Tn; t++) {
        float evA = eps_sm[t * 4 + rA];
        float evB = eps_sm[t * 4 + rB];
        float ginA = omega + aP * epsq[0] + bP * sigq[0];
        float ginB = omega + aP * epsq[1] + bP * sigq[1];
        epsq[0] = evA * evA; epsq[1] = evB * evB;
        sigq[0] = ginA;      sigq[1] = ginB;

        // ---- phase 1: full-K z & r matvecs for own 2 rows ----
        ull az0 = 0, az1 = 0, ar0 = 0, ar1 = 0;
        {
            const ulonglong2* hq = (const ulonglong2*)hp;   // [r*64 + C]
            // prefetched L2 chunks (C = 18..18+PF)
#pragma unroll
            for (int p = 0; p < PF; p++) {
                uint4 w = pf[p];
                ull za = bfpair(w.x), ra = bfpair(w.y);
                ull zb = bfpair(w.z), rb = bfpair(w.w);
                int C = NZS + p;
                ulonglong2 ha = hq[rA * 64 + C];
                ulonglong2 hb = hq[rB * 64 + C];
                az0 = fma2(za, ha.x, az0); az0 = fma2(zb, ha.y, az0);
                az1 = fma2(za, hb.x, az1); az1 = fma2(zb, hb.y, az1);
                ar0 = fma2(ra, ha.x, ar0); ar0 = fma2(rb, ha.y, ar0);
                ar1 = fma2(ra, hb.x, ar1); ar1 = fma2(rb, hb.y, ar1);
            }
            // remaining L2 chunks
#pragma unroll 8
            for (int c = PF; c < NZL; c++) {
                uint4 w = __ldg(zr_g + c * 256);
                ull za = bfpair(w.x), ra = bfpair(w.y);
                ull zb = bfpair(w.z), rb = bfpair(w.w);
                int C = NZS + c;
                ulonglong2 ha = hq[rA * 64 + C];
                ulonglong2 hb = hq[rB * 64 + C];
                az0 = fma2(za, ha.x, az0); az0 = fma2(zb, ha.y, az0);
                az1 = fma2(za, hb.x, az1); az1 = fma2(zb, hb.y, az1);
                ar0 = fma2(ra, ha.x, ar0); ar0 = fma2(rb, ha.y, ar0);
                ar1 = fma2(ra, hb.x, ar1); ar1 = fma2(rb, hb.y, ar1);
            }
            // smem chunks
#pragma unroll 6
            for (int c = 0; c < NZS; c++) {
                uint4 w = zr_s[c * 256];
                ull za = bfpair(w.x), ra = bfpair(w.y);
                ull zb = bfpair(w.z), rb = bfpair(w.w);
                ulonglong2 ha = hq[rA * 64 + c];
                ulonglong2 hb = hq[rB * 64 + c];
                az0 = fma2(za, ha.x, az0); az0 = fma2(zb, ha.y, az0);
                az1 = fma2(za, hb.x, az1); az1 = fma2(zb, hb.y, az1);
                ar0 = fma2(ra, ha.x, ar0); ar0 = fma2(rb, ha.y, ar0);
                ar1 = fma2(ra, hb.x, ar1); ar1 = fma2(rb, hb.y, ar1);
            }
        }

        // gates for own rows
        float zA = sig_ap(red2(az0) + fmaf(evA, wzw, wzb) + uzb);
        float zB = sig_ap(red2(az1) + fmaf(evB, wzw, wzb) + uzb);
        float rgA = sig_ap(red2(ar0) + fmaf(evA, wrw, wrb) + urb);
        float rgB = sig_ap(red2(ar1) + fmaf(evB, wrw, wrb) + urb);
        rhp[rA * 256 + j] = rgA * h_reg[0];
        rhp[rB * 256 + j] = rgB * h_reg[1];
        gbar(bid);

        // ---- phase 2: full-K h_tilde matvec for own 2 rows (all smem) ----
        ull ah0 = 0, ah1 = 0;
        {
            const ulonglong2* rq = (const ulonglong2*)rhp;
#pragma unroll 8
            for (int c = 0; c < NC; c++) {
                uint2 w = wh_s[c * 256];
                ull ha_ = bfpair(w.x), hb_ = bfpair(w.y);
                ulonglong2 qa = rq[rA * 64 + c];
                ulonglong2 qb = rq[rB * 64 + c];
                ah0 = fma2(ha_, qa.x, ah0); ah0 = fma2(hb_, qa.y, ah0);
                ah1 = fma2(ha_, qb.x, ah1); ah1 = fma2(hb_, qb.y, ah1);
            }
        }
        float htA = tanh_ap(red2(ah0) + fmaf(evA, whw, whb) + uhb);
        float htB = tanh_ap(red2(ah1) + fmaf(evB, whw, whb) + uhb);
        float hhA = (1.0f - zA) * htA + zA * h_reg[0];
        float hhB = (1.0f - zB) * htB + zB * h_reg[1];
        float hnA = tanh_ap(fmaf(gam, fmaf(ginA, wgw, wgb), hhA));
        float hnB = tanh_ap(fmaf(gam, fmaf(ginB, wgw, wgb), hhB));
        h_reg[0] = hnA; h_reg[1] = hnB;
        hp[rA * 256 + j] = hnA;
        hp[rB * 256 + j] = hnB;

        // prefetch next step's first PF L2 zr chunks (weights: no h dependency)
        if (t + 1 < Tn) {
#pragma unroll
            for (int p = 0; p < PF; p++) pf[p] = __ldg(zr_g + p * 256);
        }
        gbar(bid);
    }

    // stash sigma_sq for epilogue (uniform across j within group)
    if (j == 0) {
        sigq_sm[rA] = sigq[0];
        sigq_sm[rB] = sigq[1];
    }
    __syncthreads();

    // ---- epilogue: fc1 -> relu -> fc2 -> softplus -> vol ----
    float* part = eps_sm;                 // reuse: [4][256]
    {
        float acc[BT] = {0.f, 0.f, 0.f, 0.f};
        const int kb = g * 128;
        for (int k = kb; k < kb + 128; k++) {
            float f = fc1w[k * Hn + j];
#pragma unroll
            for (int r = 0; r < BT; r++) acc[r] = fmaf(hp[r * 256 + k], f, acc[r]);
        }
        if (g == 1) {
#pragma unroll
            for (int r = 0; r < BT; r++) part[r * 256 + j] = acc[r];
        }
        __syncthreads();
        if (g == 0) {
            float b1 = fc1b[j];
#pragma unroll
            for (int r = 0; r < BT; r++)
                rhp[r * 256 + j] = fmaxf(acc[r] + part[r * 256 + j] + b1, 0.0f);
        }
        __syncthreads();
    }

    if (g == 0 && j < BT * HORn) {        // 88 threads
        int r = j / HORn;
        int o = j - r * HORn;
        float s = 0.0f;
        for (int k = 0; k < Hn; k++) s = fmaf(rhp[r * 256 + k], fc2w[k * HORn + o], s);
        s += fc2b[o];
        float nn = (s > 20.0f) ? s : log1pf(expf(s));
        float vb = sqrtf(sigq_sm[r] + 1e-8f);
        float vol = vb * (1.0f + nn);
        vol = fminf(fmaxf(vol, 0.01f), 10.0f);
        out[(r0 + r) * HORn + o] = vol;
    }
    if (g == 0 && j >= BT * HORn && j < BT * HORn + BT) {
        int r = j - BT * HORn;
        out[Bn * HORn + r0 + r] = sigq_sm[r];
    }
}

extern "C" void kernel_launch(void* const* d_in, const int* in_sizes, int n_in,
                              void* d_out, int out_size) {
    const float* x    = (const float*)d_in[0];
    const float* Wzw  = (const float*)d_in[1];
    const float* Wzb  = (const float*)d_in[2];
    const float* Uzw  = (const float*)d_in[3];
    const float* Uzb  = (const float*)d_in[4];
    const float* Wrw  = (const float*)d_in[5];
    const float* Wrb  = (const float*)d_in[6];
    const float* Urw  = (const float*)d_in[7];
    const float* Urb  = (const float*)d_in[8];
    const float* Whw  = (const float*)d_in[9];
    const float* Whb  = (const float*)d_in[10];
    const float* Uhw  = (const float*)d_in[11];
    const float* Uhb  = (const float*)d_in[12];
    const float* Wgw  = (const float*)d_in[13];
    const float* Wgb  = (const float*)d_in[14];
    const float* om   = (const float*)d_in[15];
    const float* al   = (const float*)d_in[16];
    const float* be   = (const float*)d_in[17];
    const float* ga   = (const float*)d_in[18];
    const float* fc1w = (const float*)d_in[19];
    const float* fc1b = (const float*)d_in[20];
    const float* fc2w = (const float*)d_in[21];
    const float* fc2b = (const float*)d_in[22];
    float* out = (float*)d_out;

    ggru_pack_kernel<<<(NC * 256 + 255) / 256, 256>>>(Uzw, Urw, Uhw);

    cudaFuncSetAttribute(ggru_main_kernel,
                         cudaFuncAttributeMaxDynamicSharedMemorySize, SMEM_BYTES);
    ggru_main_kernel<<<NCTA, NTHR, SMEM_BYTES>>>(
        x, Wzw, Wzb, Uzb, Wrw, Wrb, Urb, Whw, Whb, Uhb,
        Wgw, Wgb, om, al, be, ga, fc1w, fc1b, fc2w, fc2b, out);
}